// round 11
// baseline (speedup 1.0000x reference)
#include <cuda_runtime.h>
#include <cuda_fp16.h>
#include <cstdint>

// Problem constants (fixed by the reference)
#define NN 50000
#define EE 800000
#define IN_C 512
#define HID_C 128
#define OUT_C 256
#define NB 196          // ceil(NN / 256)
#define NCHUNK 4
#define CHUNK 12544     // 98 * 128 (GEMM tile aligned)

// Scratch (allocation-free rule: __device__ globals)
__device__ __align__(16) __half g_h1[(size_t)NN * HID_C];    // x @ w1^T   (fp16)
__device__ __align__(16) __half g_agg1[(size_t)NN * HID_C];  // A*h1 + b1  (fp16)
__device__ __align__(16) float  g_agg2[(size_t)NN * HID_C];  // A*relu(agg1) (fp32)
__device__ int g_count[NN];
__device__ int g_rowptr[NN + 1];
__device__ int g_cursor[NN];
__device__ int g_blksum[NB];
__device__ int g_blkoff[NB];
__device__ int g_csr_src[EE];

__device__ __forceinline__ uint32_t f2tf32(float f) {
    uint32_t r;
    asm("cvt.rna.tf32.f32 %0, %1;" : "=r"(r) : "f"(f));
    return r;
}

// ---------------------------------------------------------------------------
// TF32 tensor-core GEMM with 2-stage cp.async pipeline.
// C[m][n] = sum_k A[m][k] * W[n][k] (+ bias[n]);  W is [N,K] row-major.
// Grid: x = N-blocks (fastest -> A-tile L2 reuse), y = M-blocks.
// ---------------------------------------------------------------------------
template <int K, int NTOT, bool BIAS, bool HALF_OUT>
__global__ __launch_bounds__(256)
void gemm_tf32(const float* __restrict__ A, const float* __restrict__ W,
               const float* __restrict__ bias, void* __restrict__ Cv, int M) {
    constexpr int BM = 128, BN = 64, BK = 32, LDS = BK + 4;
    constexpr int TILES = K / BK;
    __shared__ float As[2][BM][LDS];
    __shared__ float Bs[2][BN][LDS];

    const int tid = threadIdx.x;
    const int lane = tid & 31;
    const int wid = tid >> 5;
    const int warp_m = wid >> 1;
    const int warp_n = wid & 1;
    const int bm = blockIdx.y * BM;
    const int bn = blockIdx.x * BN;
    const int a_row = tid >> 3;
    const int a_c4 = (tid & 7) * 4;

    float acc[2][4][4];
#pragma unroll
    for (int mf = 0; mf < 2; mf++)
#pragma unroll
        for (int nf = 0; nf < 4; nf++)
#pragma unroll
            for (int r = 0; r < 4; r++) acc[mf][nf][r] = 0.0f;

    auto load_stage = [&](int stage, int k0) {
#pragma unroll
        for (int i = 0; i < 4; i++) {
            int row = a_row + i * 32;
            const float* gp = A + (size_t)(bm + row) * K + k0 + a_c4;
            uint32_t sa = (uint32_t)__cvta_generic_to_shared(&As[stage][row][a_c4]);
            int sz = (bm + row < M) ? 16 : 0;
            asm volatile("cp.async.cg.shared.global [%0], [%1], 16, %2;"
                         :: "r"(sa), "l"(gp), "r"(sz));
        }
#pragma unroll
        for (int i = 0; i < 2; i++) {
            int row = a_row + i * 32;
            const float* gp = W + (size_t)(bn + row) * K + k0 + a_c4;
            uint32_t sa = (uint32_t)__cvta_generic_to_shared(&Bs[stage][row][a_c4]);
            asm volatile("cp.async.cg.shared.global [%0], [%1], 16;"
                         :: "r"(sa), "l"(gp));
        }
        asm volatile("cp.async.commit_group;");
    };

    load_stage(0, 0);

    for (int t = 0; t < TILES; t++) {
        const int buf = t & 1;
        if (t + 1 < TILES) {
            load_stage(buf ^ 1, (t + 1) * BK);
            asm volatile("cp.async.wait_group 1;");
        } else {
            asm volatile("cp.async.wait_group 0;");
        }
        __syncthreads();

#pragma unroll
        for (int ks = 0; ks < BK / 8; ks++) {
            const int kb = ks * 8;
            const int kc = kb + (lane & 3);
            uint32_t a[2][4], b[4][2];
#pragma unroll
            for (int mf = 0; mf < 2; mf++) {
                int mr = warp_m * 32 + mf * 16 + (lane >> 2);
                a[mf][0] = f2tf32(As[buf][mr][kc]);
                a[mf][1] = f2tf32(As[buf][mr + 8][kc]);
                a[mf][2] = f2tf32(As[buf][mr][kc + 4]);
                a[mf][3] = f2tf32(As[buf][mr + 8][kc + 4]);
            }
#pragma unroll
            for (int nf = 0; nf < 4; nf++) {
                int nr = warp_n * 32 + nf * 8 + (lane >> 2);
                b[nf][0] = f2tf32(Bs[buf][nr][kc]);
                b[nf][1] = f2tf32(Bs[buf][nr][kc + 4]);
            }
#pragma unroll
            for (int mf = 0; mf < 2; mf++)
#pragma unroll
                for (int nf = 0; nf < 4; nf++) {
                    asm volatile(
                        "mma.sync.aligned.m16n8k8.row.col.f32.tf32.tf32.f32 "
                        "{%0,%1,%2,%3}, {%4,%5,%6,%7}, {%8,%9}, {%0,%1,%2,%3};\n"
                        : "+f"(acc[mf][nf][0]), "+f"(acc[mf][nf][1]),
                          "+f"(acc[mf][nf][2]), "+f"(acc[mf][nf][3])
                        : "r"(a[mf][0]), "r"(a[mf][1]), "r"(a[mf][2]), "r"(a[mf][3]),
                          "r"(b[nf][0]), "r"(b[nf][1]));
                }
        }
        __syncthreads();
    }

#pragma unroll
    for (int mf = 0; mf < 2; mf++) {
#pragma unroll
        for (int nf = 0; nf < 4; nf++) {
            int gr = bm + warp_m * 32 + mf * 16 + (lane >> 2);
            int gc = bn + warp_n * 32 + nf * 8 + 2 * (lane & 3);
            float b0 = 0.f, b1 = 0.f;
            if (BIAS) { b0 = __ldg(bias + gc); b1 = __ldg(bias + gc + 1); }
            if (HALF_OUT) {
                __half* C = (__half*)Cv;
                if (gr < M)
                    *reinterpret_cast<__half2*>(C + (size_t)gr * NTOT + gc) =
                        __floats2half2_rn(acc[mf][nf][0] + b0, acc[mf][nf][1] + b1);
                if (gr + 8 < M)
                    *reinterpret_cast<__half2*>(C + (size_t)(gr + 8) * NTOT + gc) =
                        __floats2half2_rn(acc[mf][nf][2] + b0, acc[mf][nf][3] + b1);
            } else {
                float* C = (float*)Cv;
                if (gr < M)
                    *reinterpret_cast<float2*>(C + (size_t)gr * NTOT + gc) =
                        make_float2(acc[mf][nf][0] + b0, acc[mf][nf][1] + b1);
                if (gr + 8 < M)
                    *reinterpret_cast<float2*>(C + (size_t)(gr + 8) * NTOT + gc) =
                        make_float2(acc[mf][nf][2] + b0, acc[mf][nf][3] + b1);
            }
        }
    }
}

// ---------------------------------------------------------------------------
// CSR construction: histogram -> block sums -> scan -> row_ptr/cursor -> fill
// ---------------------------------------------------------------------------
__global__ void hist_dst(const int* __restrict__ dst, int* __restrict__ count, int E) {
    int i = blockIdx.x * blockDim.x + threadIdx.x;
    int stride = gridDim.x * blockDim.x;
    for (; i < E; i += stride) {
        int d = dst[i];
        if ((unsigned)d < NN) atomicAdd(count + d, 1);
    }
}

__global__ __launch_bounds__(256)
void block_sums(const int* __restrict__ count, int* __restrict__ bsum) {
    __shared__ int sh[256];
    int i = blockIdx.x * 256 + threadIdx.x;
    sh[threadIdx.x] = (i < NN) ? count[i] : 0;
    __syncthreads();
    for (int off = 128; off > 0; off >>= 1) {
        if (threadIdx.x < off) sh[threadIdx.x] += sh[threadIdx.x + off];
        __syncthreads();
    }
    if (threadIdx.x == 0) bsum[blockIdx.x] = sh[0];
}

__global__ __launch_bounds__(256)
void scan_block_sums(const int* __restrict__ bsum, int* __restrict__ boff,
                     int* __restrict__ rowptr_last) {
    __shared__ int sh[256];
    int t = threadIdx.x;
    int v = (t < NB) ? bsum[t] : 0;
    sh[t] = v;
    __syncthreads();
    for (int off = 1; off < 256; off <<= 1) {
        int add = (t >= off) ? sh[t - off] : 0;
        __syncthreads();
        sh[t] += add;
        __syncthreads();
    }
    if (t < NB) boff[t] = sh[t] - v;
    if (t == 255) *rowptr_last = sh[255];
}

__global__ __launch_bounds__(256)
void write_rowptr(const int* __restrict__ count, const int* __restrict__ boff,
                  int* __restrict__ rowptr, int* __restrict__ cursor) {
    __shared__ int sh[256];
    int i = blockIdx.x * 256 + threadIdx.x;
    int t = threadIdx.x;
    int v = (i < NN) ? count[i] : 0;
    sh[t] = v;
    __syncthreads();
    for (int off = 1; off < 256; off <<= 1) {
        int add = (t >= off) ? sh[t - off] : 0;
        __syncthreads();
        sh[t] += add;
        __syncthreads();
    }
    if (i < NN) {
        int rp = boff[blockIdx.x] + sh[t] - v;
        rowptr[i] = rp;
        cursor[i] = rp;
    }
}

__global__ void fill_csr(const int* __restrict__ ei, int* __restrict__ cursor,
                         int* __restrict__ csr_src, int E) {
    const int* __restrict__ src = ei;
    const int* __restrict__ dst = ei + E;
    int i = blockIdx.x * blockDim.x + threadIdx.x;
    int stride = gridDim.x * blockDim.x;
    for (; i < E; i += stride) {
        int d = dst[i];
        if ((unsigned)d >= NN) continue;
        int pos = atomicAdd(cursor + d, 1);
        csr_src[pos] = src[i];
    }
}

// ---------------------------------------------------------------------------
// fp16 gather aggregation (R9 version + node-range offset).
// Rows are 128 halves = 32 uint2; lane owns 4 halves. fp32 accumulation.
// Processes nodes [node0, node0+nnodes).
// ---------------------------------------------------------------------------
__device__ __forceinline__ void acc_u2(float4& acc, uint2 u, bool relu) {
    float2 fa = __half22float2(*reinterpret_cast<__half2*>(&u.x));
    float2 fb = __half22float2(*reinterpret_cast<__half2*>(&u.y));
    if (relu) {
        fa.x = fmaxf(fa.x, 0.f); fa.y = fmaxf(fa.y, 0.f);
        fb.x = fmaxf(fb.x, 0.f); fb.y = fmaxf(fb.y, 0.f);
    }
    acc.x += fa.x; acc.y += fa.y; acc.z += fb.x; acc.w += fb.y;
}

template <bool RELU, bool BIAS, bool HALF_OUT>
__global__ __launch_bounds__(256)
void agg_gather_h16(const uint2* __restrict__ H, const int* __restrict__ rowptr,
                    const int* __restrict__ csr_src, const float* __restrict__ bias,
                    void* __restrict__ OUT, int node0, int nnodes) {
    const int w = (blockIdx.x * blockDim.x + threadIdx.x) >> 5;
    const int lane = threadIdx.x & 31;
    if (w >= nnodes) return;
    const int node = node0 + w;

    const int start = __ldg(rowptr + node);
    const int end = __ldg(rowptr + node + 1);

    float4 acc = BIAS ? __ldg(reinterpret_cast<const float4*>(bias) + lane)
                      : make_float4(0.f, 0.f, 0.f, 0.f);

    int i = start;
    for (; i + 4 <= end; i += 4) {
        int s0 = __ldg(csr_src + i);
        int s1 = __ldg(csr_src + i + 1);
        int s2 = __ldg(csr_src + i + 2);
        int s3 = __ldg(csr_src + i + 3);
        uint2 u0 = __ldg(H + (size_t)s0 * 32 + lane);
        uint2 u1 = __ldg(H + (size_t)s1 * 32 + lane);
        uint2 u2 = __ldg(H + (size_t)s2 * 32 + lane);
        uint2 u3 = __ldg(H + (size_t)s3 * 32 + lane);
        acc_u2(acc, u0, RELU);
        acc_u2(acc, u1, RELU);
        acc_u2(acc, u2, RELU);
        acc_u2(acc, u3, RELU);
    }
    for (; i < end; i++) {
        int s = __ldg(csr_src + i);
        acc_u2(acc, __ldg(H + (size_t)s * 32 + lane), RELU);
    }

    if (HALF_OUT) {
        __half2 h0 = __floats2half2_rn(acc.x, acc.y);
        __half2 h1 = __floats2half2_rn(acc.z, acc.w);
        uint2 o;
        o.x = *reinterpret_cast<uint32_t*>(&h0);
        o.y = *reinterpret_cast<uint32_t*>(&h1);
        reinterpret_cast<uint2*>(OUT)[(size_t)node * 32 + lane] = o;
    } else {
        reinterpret_cast<float4*>(OUT)[(size_t)node * 32 + lane] = acc;
    }
}

extern "C" void kernel_launch(void* const* d_in, const int* in_sizes, int n_in,
                              void* d_out, int out_size) {
    const float* x = (const float*)d_in[0];
    const int* edge_index = (const int*)d_in[1];
    const float* w1 = (const float*)d_in[2];
    const float* b1 = (const float*)d_in[3];
    const float* w2 = (const float*)d_in[4];
    const float* b2 = (const float*)d_in[5];
    float* out = (float*)d_out;

    __half* h1;   cudaGetSymbolAddress((void**)&h1, g_h1);
    __half* agg1; cudaGetSymbolAddress((void**)&agg1, g_agg1);
    float* agg2;  cudaGetSymbolAddress((void**)&agg2, g_agg2);
    int* count;   cudaGetSymbolAddress((void**)&count, g_count);
    int* rowptr;  cudaGetSymbolAddress((void**)&rowptr, g_rowptr);
    int* cursor;  cudaGetSymbolAddress((void**)&cursor, g_cursor);
    int* bsum;    cudaGetSymbolAddress((void**)&bsum, g_blksum);
    int* boff;    cudaGetSymbolAddress((void**)&boff, g_blkoff);
    int* csr_src; cudaGetSymbolAddress((void**)&csr_src, g_csr_src);

    static cudaStream_t s2 = nullptr;
    static cudaEvent_t ev_fork = nullptr, ev_join = nullptr, ev_done = nullptr;
    static cudaEvent_t ev_chunk[NCHUNK] = {};
    if (s2 == nullptr) {
        cudaStreamCreateWithFlags(&s2, cudaStreamNonBlocking);
        cudaEventCreateWithFlags(&ev_fork, cudaEventDisableTiming);
        cudaEventCreateWithFlags(&ev_join, cudaEventDisableTiming);
        cudaEventCreateWithFlags(&ev_done, cudaEventDisableTiming);
        for (int c = 0; c < NCHUNK; c++)
            cudaEventCreateWithFlags(&ev_chunk[c], cudaEventDisableTiming);
    }

    // ---- Fork: CSR build on s2, concurrent with GEMM1 ----
    cudaEventRecord(ev_fork, 0);
    cudaStreamWaitEvent(s2, ev_fork, 0);

    cudaMemsetAsync(count, 0, NN * sizeof(int), s2);
    hist_dst<<<1024, 256, 0, s2>>>(edge_index + EE, count, EE);
    block_sums<<<NB, 256, 0, s2>>>(count, bsum);
    scan_block_sums<<<1, 256, 0, s2>>>(bsum, boff, rowptr + NN);
    write_rowptr<<<NB, 256, 0, s2>>>(count, boff, rowptr, cursor);
    fill_csr<<<1024, 256, 0, s2>>>(edge_index, cursor, csr_src, EE);
    cudaEventRecord(ev_join, s2);

    // ---- h1 = x @ w1^T  -> fp16   (main stream, overlaps CSR build) ----
    {
        dim3 grid(HID_C / 64, (NN + 127) / 128);
        gemm_tf32<IN_C, HID_C, false, true><<<grid, 256>>>(x, w1, nullptr, h1, NN);
    }

    // ---- Join: gathers need both h1 and the CSR ----
    cudaStreamWaitEvent(0, ev_join, 0);

    // ---- agg1[n] = fp16(b1 + sum h1[src in(n)])  (full; gather2 needs all) ----
    agg_gather_h16<false, true, true><<<(NN * 32 + 255) / 256, 256>>>(
        (const uint2*)h1, rowptr, csr_src, b1, agg1, 0, NN);

    // ---- Chunk-pipelined: gather2 chunk c (main)  ->  GEMM2 chunk c (s2) ----
    for (int c = 0; c < NCHUNK; c++) {
        int start = c * CHUNK;
        int len = (start + CHUNK <= NN) ? CHUNK : (NN - start);
        agg_gather_h16<true, false, false><<<(len * 32 + 255) / 256, 256>>>(
            (const uint2*)agg1, rowptr, csr_src, nullptr, agg2, start, len);
        cudaEventRecord(ev_chunk[c], 0);
        cudaStreamWaitEvent(s2, ev_chunk[c], 0);
        dim3 grid(OUT_C / 64, (len + 127) / 128);
        gemm_tf32<HID_C, OUT_C, true, false><<<grid, 256, 0, s2>>>(
            agg2 + (size_t)start * HID_C, w2, b2,
            out + (size_t)start * OUT_C, len);
    }

    // ---- Final join: capture must end with s2 merged back ----
    cudaEventRecord(ev_done, s2);
    cudaStreamWaitEvent(0, ev_done, 0);
}

// round 12
// speedup vs baseline: 1.5406x; 1.5406x over previous
#include <cuda_runtime.h>
#include <cuda_fp16.h>
#include <cstdint>

// Problem constants (fixed by the reference)
#define NN 50000
#define EE 800000
#define IN_C 512
#define HID_C 128
#define OUT_C 256
#define NB 196          // ceil(NN / 256)

// Scratch (allocation-free rule: __device__ globals)
__device__ __align__(16) __half g_h1[(size_t)NN * HID_C];    // x @ w1^T   (fp16)
__device__ __align__(16) __half g_agg1[(size_t)NN * HID_C];  // A*h1 + b1  (fp16)
__device__ __align__(16) float  g_agg2[(size_t)NN * HID_C];  // A*relu(agg1) (fp32)
__device__ int g_count[NN];
__device__ int g_rowptr[NN + 1];
__device__ int g_cursor[NN];
__device__ int g_blksum[NB];
__device__ int g_blkoff[NB];
__device__ int g_csr_src[EE];

__device__ __forceinline__ uint32_t f2tf32(float f) {
    uint32_t r;
    asm("cvt.rna.tf32.f32 %0, %1;" : "=r"(r) : "f"(f));
    return r;
}

// ---------------------------------------------------------------------------
// TF32 tensor-core GEMM with 2-stage cp.async pipeline.
// C[m][n] = sum_k A[m][k] * W[n][k] (+ bias[n]);  W is [N,K] row-major.
// Grid: x = N-blocks (fastest -> A-tile L2 reuse), y = M-blocks.
// ---------------------------------------------------------------------------
template <int K, int NTOT, bool BIAS, bool HALF_OUT>
__global__ __launch_bounds__(256)
void gemm_tf32(const float* __restrict__ A, const float* __restrict__ W,
               const float* __restrict__ bias, void* __restrict__ Cv, int M) {
    constexpr int BM = 128, BN = 64, BK = 32, LDS = BK + 4;
    constexpr int TILES = K / BK;
    __shared__ float As[2][BM][LDS];
    __shared__ float Bs[2][BN][LDS];

    const int tid = threadIdx.x;
    const int lane = tid & 31;
    const int wid = tid >> 5;
    const int warp_m = wid >> 1;
    const int warp_n = wid & 1;
    const int bm = blockIdx.y * BM;
    const int bn = blockIdx.x * BN;
    const int a_row = tid >> 3;
    const int a_c4 = (tid & 7) * 4;

    float acc[2][4][4];
#pragma unroll
    for (int mf = 0; mf < 2; mf++)
#pragma unroll
        for (int nf = 0; nf < 4; nf++)
#pragma unroll
            for (int r = 0; r < 4; r++) acc[mf][nf][r] = 0.0f;

    auto load_stage = [&](int stage, int k0) {
#pragma unroll
        for (int i = 0; i < 4; i++) {
            int row = a_row + i * 32;
            const float* gp = A + (size_t)(bm + row) * K + k0 + a_c4;
            uint32_t sa = (uint32_t)__cvta_generic_to_shared(&As[stage][row][a_c4]);
            int sz = (bm + row < M) ? 16 : 0;
            asm volatile("cp.async.cg.shared.global [%0], [%1], 16, %2;"
                         :: "r"(sa), "l"(gp), "r"(sz));
        }
#pragma unroll
        for (int i = 0; i < 2; i++) {
            int row = a_row + i * 32;
            const float* gp = W + (size_t)(bn + row) * K + k0 + a_c4;
            uint32_t sa = (uint32_t)__cvta_generic_to_shared(&Bs[stage][row][a_c4]);
            asm volatile("cp.async.cg.shared.global [%0], [%1], 16;"
                         :: "r"(sa), "l"(gp));
        }
        asm volatile("cp.async.commit_group;");
    };

    load_stage(0, 0);

    for (int t = 0; t < TILES; t++) {
        const int buf = t & 1;
        if (t + 1 < TILES) {
            load_stage(buf ^ 1, (t + 1) * BK);
            asm volatile("cp.async.wait_group 1;");
        } else {
            asm volatile("cp.async.wait_group 0;");
        }
        __syncthreads();

#pragma unroll
        for (int ks = 0; ks < BK / 8; ks++) {
            const int kb = ks * 8;
            const int kc = kb + (lane & 3);
            uint32_t a[2][4], b[4][2];
#pragma unroll
            for (int mf = 0; mf < 2; mf++) {
                int mr = warp_m * 32 + mf * 16 + (lane >> 2);
                a[mf][0] = f2tf32(As[buf][mr][kc]);
                a[mf][1] = f2tf32(As[buf][mr + 8][kc]);
                a[mf][2] = f2tf32(As[buf][mr][kc + 4]);
                a[mf][3] = f2tf32(As[buf][mr + 8][kc + 4]);
            }
#pragma unroll
            for (int nf = 0; nf < 4; nf++) {
                int nr = warp_n * 32 + nf * 8 + (lane >> 2);
                b[nf][0] = f2tf32(Bs[buf][nr][kc]);
                b[nf][1] = f2tf32(Bs[buf][nr][kc + 4]);
            }
#pragma unroll
            for (int mf = 0; mf < 2; mf++)
#pragma unroll
                for (int nf = 0; nf < 4; nf++) {
                    asm volatile(
                        "mma.sync.aligned.m16n8k8.row.col.f32.tf32.tf32.f32 "
                        "{%0,%1,%2,%3}, {%4,%5,%6,%7}, {%8,%9}, {%0,%1,%2,%3};\n"
                        : "+f"(acc[mf][nf][0]), "+f"(acc[mf][nf][1]),
                          "+f"(acc[mf][nf][2]), "+f"(acc[mf][nf][3])
                        : "r"(a[mf][0]), "r"(a[mf][1]), "r"(a[mf][2]), "r"(a[mf][3]),
                          "r"(b[nf][0]), "r"(b[nf][1]));
                }
        }
        __syncthreads();
    }

#pragma unroll
    for (int mf = 0; mf < 2; mf++) {
#pragma unroll
        for (int nf = 0; nf < 4; nf++) {
            int gr = bm + warp_m * 32 + mf * 16 + (lane >> 2);
            int gc = bn + warp_n * 32 + nf * 8 + 2 * (lane & 3);
            float b0 = 0.f, b1 = 0.f;
            if (BIAS) { b0 = __ldg(bias + gc); b1 = __ldg(bias + gc + 1); }
            if (HALF_OUT) {
                __half* C = (__half*)Cv;
                if (gr < M)
                    *reinterpret_cast<__half2*>(C + (size_t)gr * NTOT + gc) =
                        __floats2half2_rn(acc[mf][nf][0] + b0, acc[mf][nf][1] + b1);
                if (gr + 8 < M)
                    *reinterpret_cast<__half2*>(C + (size_t)(gr + 8) * NTOT + gc) =
                        __floats2half2_rn(acc[mf][nf][2] + b0, acc[mf][nf][3] + b1);
            } else {
                float* C = (float*)Cv;
                if (gr < M)
                    *reinterpret_cast<float2*>(C + (size_t)gr * NTOT + gc) =
                        make_float2(acc[mf][nf][0] + b0, acc[mf][nf][1] + b1);
                if (gr + 8 < M)
                    *reinterpret_cast<float2*>(C + (size_t)(gr + 8) * NTOT + gc) =
                        make_float2(acc[mf][nf][2] + b0, acc[mf][nf][3] + b1);
            }
        }
    }
}

// ---------------------------------------------------------------------------
// CSR construction: histogram -> block sums -> scan -> row_ptr/cursor -> fill
// ---------------------------------------------------------------------------
__global__ void hist_dst(const int* __restrict__ dst, int* __restrict__ count, int E) {
    int i = blockIdx.x * blockDim.x + threadIdx.x;
    int stride = gridDim.x * blockDim.x;
    for (; i < E; i += stride) {
        int d = dst[i];
        if ((unsigned)d < NN) atomicAdd(count + d, 1);
    }
}

__global__ __launch_bounds__(256)
void block_sums(const int* __restrict__ count, int* __restrict__ bsum) {
    __shared__ int sh[256];
    int i = blockIdx.x * 256 + threadIdx.x;
    sh[threadIdx.x] = (i < NN) ? count[i] : 0;
    __syncthreads();
    for (int off = 128; off > 0; off >>= 1) {
        if (threadIdx.x < off) sh[threadIdx.x] += sh[threadIdx.x + off];
        __syncthreads();
    }
    if (threadIdx.x == 0) bsum[blockIdx.x] = sh[0];
}

__global__ __launch_bounds__(256)
void scan_block_sums(const int* __restrict__ bsum, int* __restrict__ boff,
                     int* __restrict__ rowptr_last) {
    __shared__ int sh[256];
    int t = threadIdx.x;
    int v = (t < NB) ? bsum[t] : 0;
    sh[t] = v;
    __syncthreads();
    for (int off = 1; off < 256; off <<= 1) {
        int add = (t >= off) ? sh[t - off] : 0;
        __syncthreads();
        sh[t] += add;
        __syncthreads();
    }
    if (t < NB) boff[t] = sh[t] - v;
    if (t == 255) *rowptr_last = sh[255];
}

__global__ __launch_bounds__(256)
void write_rowptr(const int* __restrict__ count, const int* __restrict__ boff,
                  int* __restrict__ rowptr, int* __restrict__ cursor) {
    __shared__ int sh[256];
    int i = blockIdx.x * 256 + threadIdx.x;
    int t = threadIdx.x;
    int v = (i < NN) ? count[i] : 0;
    sh[t] = v;
    __syncthreads();
    for (int off = 1; off < 256; off <<= 1) {
        int add = (t >= off) ? sh[t - off] : 0;
        __syncthreads();
        sh[t] += add;
        __syncthreads();
    }
    if (i < NN) {
        int rp = boff[blockIdx.x] + sh[t] - v;
        rowptr[i] = rp;
        cursor[i] = rp;
    }
}

__global__ void fill_csr(const int* __restrict__ ei, int* __restrict__ cursor,
                         int* __restrict__ csr_src, int E) {
    const int* __restrict__ src = ei;
    const int* __restrict__ dst = ei + E;
    int i = blockIdx.x * blockDim.x + threadIdx.x;
    int stride = gridDim.x * blockDim.x;
    for (; i < E; i += stride) {
        int d = dst[i];
        if ((unsigned)d >= NN) continue;
        int pos = atomicAdd(cursor + d, 1);
        csr_src[pos] = src[i];
    }
}

// ---------------------------------------------------------------------------
// fp16 gather aggregation (warp per node). Rows are 128 halves = 32 uint2.
// 8-wide unrolled body for MLP; fp32 accumulation.
// ---------------------------------------------------------------------------
__device__ __forceinline__ void acc_u2(float4& acc, uint2 u, bool relu) {
    float2 fa = __half22float2(*reinterpret_cast<__half2*>(&u.x));
    float2 fb = __half22float2(*reinterpret_cast<__half2*>(&u.y));
    if (relu) {
        fa.x = fmaxf(fa.x, 0.f); fa.y = fmaxf(fa.y, 0.f);
        fb.x = fmaxf(fb.x, 0.f); fb.y = fmaxf(fb.y, 0.f);
    }
    acc.x += fa.x; acc.y += fa.y; acc.z += fb.x; acc.w += fb.y;
}

template <bool RELU, bool BIAS, bool HALF_OUT>
__global__ __launch_bounds__(256)
void agg_gather_h16(const uint2* __restrict__ H, const int* __restrict__ rowptr,
                    const int* __restrict__ csr_src, const float* __restrict__ bias,
                    void* __restrict__ OUT) {
    const int warp = (blockIdx.x * blockDim.x + threadIdx.x) >> 5;
    const int lane = threadIdx.x & 31;
    if (warp >= NN) return;

    const int start = __ldg(rowptr + warp);
    const int end = __ldg(rowptr + warp + 1);

    float4 acc = BIAS ? __ldg(reinterpret_cast<const float4*>(bias) + lane)
                      : make_float4(0.f, 0.f, 0.f, 0.f);

    int i = start;
    // 8-wide: 8 independent index loads then 8 independent row loads in flight
    for (; i + 8 <= end; i += 8) {
        int s[8];
#pragma unroll
        for (int j = 0; j < 8; j++) s[j] = __ldg(csr_src + i + j);
        uint2 u[8];
#pragma unroll
        for (int j = 0; j < 8; j++) u[j] = __ldg(H + (size_t)s[j] * 32 + lane);
#pragma unroll
        for (int j = 0; j < 8; j++) acc_u2(acc, u[j], RELU);
    }
    for (; i + 4 <= end; i += 4) {
        int s0 = __ldg(csr_src + i);
        int s1 = __ldg(csr_src + i + 1);
        int s2 = __ldg(csr_src + i + 2);
        int s3 = __ldg(csr_src + i + 3);
        uint2 u0 = __ldg(H + (size_t)s0 * 32 + lane);
        uint2 u1 = __ldg(H + (size_t)s1 * 32 + lane);
        uint2 u2 = __ldg(H + (size_t)s2 * 32 + lane);
        uint2 u3 = __ldg(H + (size_t)s3 * 32 + lane);
        acc_u2(acc, u0, RELU);
        acc_u2(acc, u1, RELU);
        acc_u2(acc, u2, RELU);
        acc_u2(acc, u3, RELU);
    }
    for (; i < end; i++) {
        int s = __ldg(csr_src + i);
        acc_u2(acc, __ldg(H + (size_t)s * 32 + lane), RELU);
    }

    if (HALF_OUT) {
        __half2 h0 = __floats2half2_rn(acc.x, acc.y);
        __half2 h1 = __floats2half2_rn(acc.z, acc.w);
        uint2 o;
        o.x = *reinterpret_cast<uint32_t*>(&h0);
        o.y = *reinterpret_cast<uint32_t*>(&h1);
        reinterpret_cast<uint2*>(OUT)[(size_t)warp * 32 + lane] = o;
    } else {
        reinterpret_cast<float4*>(OUT)[(size_t)warp * 32 + lane] = acc;
    }
}

extern "C" void kernel_launch(void* const* d_in, const int* in_sizes, int n_in,
                              void* d_out, int out_size) {
    const float* x = (const float*)d_in[0];
    const int* edge_index = (const int*)d_in[1];
    const float* w1 = (const float*)d_in[2];
    const float* b1 = (const float*)d_in[3];
    const float* w2 = (const float*)d_in[4];
    const float* b2 = (const float*)d_in[5];
    float* out = (float*)d_out;

    __half* h1;   cudaGetSymbolAddress((void**)&h1, g_h1);
    __half* agg1; cudaGetSymbolAddress((void**)&agg1, g_agg1);
    float* agg2;  cudaGetSymbolAddress((void**)&agg2, g_agg2);
    int* count;   cudaGetSymbolAddress((void**)&count, g_count);
    int* rowptr;  cudaGetSymbolAddress((void**)&rowptr, g_rowptr);
    int* cursor;  cudaGetSymbolAddress((void**)&cursor, g_cursor);
    int* bsum;    cudaGetSymbolAddress((void**)&bsum, g_blksum);
    int* boff;    cudaGetSymbolAddress((void**)&boff, g_blkoff);
    int* csr_src; cudaGetSymbolAddress((void**)&csr_src, g_csr_src);

    static cudaStream_t s2 = nullptr;
    static cudaEvent_t ev_fork = nullptr, ev_join = nullptr;
    if (s2 == nullptr) {
        cudaStreamCreateWithFlags(&s2, cudaStreamNonBlocking);
        cudaEventCreateWithFlags(&ev_fork, cudaEventDisableTiming);
        cudaEventCreateWithFlags(&ev_join, cudaEventDisableTiming);
    }

    // ---- Fork: CSR build on s2, concurrent with GEMM1 ----
    cudaEventRecord(ev_fork, 0);
    cudaStreamWaitEvent(s2, ev_fork, 0);

    cudaMemsetAsync(count, 0, NN * sizeof(int), s2);
    hist_dst<<<1024, 256, 0, s2>>>(edge_index + EE, count, EE);
    block_sums<<<NB, 256, 0, s2>>>(count, bsum);
    scan_block_sums<<<1, 256, 0, s2>>>(bsum, boff, rowptr + NN);
    write_rowptr<<<NB, 256, 0, s2>>>(count, boff, rowptr, cursor);
    fill_csr<<<1024, 256, 0, s2>>>(edge_index, cursor, csr_src, EE);
    cudaEventRecord(ev_join, s2);

    // ---- h1 = x @ w1^T  -> fp16   (main stream, overlaps CSR build) ----
    {
        dim3 grid(HID_C / 64, (NN + 127) / 128);
        gemm_tf32<IN_C, HID_C, false, true><<<grid, 256>>>(x, w1, nullptr, h1, NN);
    }

    // ---- Join: gathers need both h1 and the CSR ----
    cudaStreamWaitEvent(0, ev_join, 0);

    // ---- agg1[n] = fp16(b1 + sum h1[src in(n)]) ----
    agg_gather_h16<false, true, true><<<(NN * 32 + 255) / 256, 256>>>(
        (const uint2*)h1, rowptr, csr_src, b1, agg1);
    // ---- agg2[n] = fp32 sum relu(agg1[src in(n)]) ----
    agg_gather_h16<true, false, false><<<(NN * 32 + 255) / 256, 256>>>(
        (const uint2*)agg1, rowptr, csr_src, nullptr, agg2);
    // ---- out = agg2 @ w2^T + b2 ----
    {
        dim3 grid(OUT_C / 64, (NN + 127) / 128);
        gemm_tf32<HID_C, OUT_C, true, false><<<grid, 256>>>(agg2, w2, b2, out, NN);
    }
}

// round 13
// speedup vs baseline: 1.5962x; 1.0361x over previous
#include <cuda_runtime.h>
#include <cuda_fp16.h>
#include <cstdint>

// Problem constants (fixed by the reference)
#define NN 50000
#define EE 800000
#define IN_C 512
#define HID_C 128
#define OUT_C 256
#define NB 196          // ceil(NN / 256)

// Scratch (allocation-free rule: __device__ globals)
__device__ __align__(16) __half g_h1[(size_t)NN * HID_C];    // x @ w1^T   (fp16)
__device__ __align__(16) __half g_agg1[(size_t)NN * HID_C];  // A*h1 + b1  (fp16)
__device__ __align__(16) __half g_agg2[(size_t)NN * HID_C];  // A*relu(agg1) (fp16)
__device__ int g_count[NN];
__device__ int g_rowptr[NN + 1];
__device__ int g_cursor[NN];
__device__ int g_blksum[NB];
__device__ int g_csr_src[EE];

__device__ __forceinline__ uint32_t f2tf32(float f) {
    uint32_t r;
    asm("cvt.rna.tf32.f32 %0, %1;" : "=r"(r) : "f"(f));
    return r;
}
__device__ __forceinline__ uint32_t pack_f16x2(float lo, float hi) {
    uint32_t r;
    asm("cvt.rn.f16x2.f32 %0, %1, %2;" : "=r"(r) : "f"(hi), "f"(lo));
    return r;
}

// ---------------------------------------------------------------------------
// TF32 tensor-core GEMM (fp32 A) with 2-stage cp.async pipeline. (GEMM1)
// C[m][n] = sum_k A[m][k] * W[n][k]; W is [N,K] row-major.
// ---------------------------------------------------------------------------
template <int K, int NTOT, bool BIAS, bool HALF_OUT>
__global__ __launch_bounds__(256)
void gemm_tf32(const float* __restrict__ A, const float* __restrict__ W,
               const float* __restrict__ bias, void* __restrict__ Cv, int M) {
    constexpr int BM = 128, BN = 64, BK = 32, LDS = BK + 4;
    constexpr int TILES = K / BK;
    __shared__ float As[2][BM][LDS];
    __shared__ float Bs[2][BN][LDS];

    const int tid = threadIdx.x;
    const int lane = tid & 31;
    const int wid = tid >> 5;
    const int warp_m = wid >> 1;
    const int warp_n = wid & 1;
    const int bm = blockIdx.y * BM;
    const int bn = blockIdx.x * BN;
    const int a_row = tid >> 3;
    const int a_c4 = (tid & 7) * 4;

    float acc[2][4][4];
#pragma unroll
    for (int mf = 0; mf < 2; mf++)
#pragma unroll
        for (int nf = 0; nf < 4; nf++)
#pragma unroll
            for (int r = 0; r < 4; r++) acc[mf][nf][r] = 0.0f;

    auto load_stage = [&](int stage, int k0) {
#pragma unroll
        for (int i = 0; i < 4; i++) {
            int row = a_row + i * 32;
            const float* gp = A + (size_t)(bm + row) * K + k0 + a_c4;
            uint32_t sa = (uint32_t)__cvta_generic_to_shared(&As[stage][row][a_c4]);
            int sz = (bm + row < M) ? 16 : 0;
            asm volatile("cp.async.cg.shared.global [%0], [%1], 16, %2;"
                         :: "r"(sa), "l"(gp), "r"(sz));
        }
#pragma unroll
        for (int i = 0; i < 2; i++) {
            int row = a_row + i * 32;
            const float* gp = W + (size_t)(bn + row) * K + k0 + a_c4;
            uint32_t sa = (uint32_t)__cvta_generic_to_shared(&Bs[stage][row][a_c4]);
            asm volatile("cp.async.cg.shared.global [%0], [%1], 16;"
                         :: "r"(sa), "l"(gp));
        }
        asm volatile("cp.async.commit_group;");
    };

    load_stage(0, 0);

    for (int t = 0; t < TILES; t++) {
        const int buf = t & 1;
        if (t + 1 < TILES) {
            load_stage(buf ^ 1, (t + 1) * BK);
            asm volatile("cp.async.wait_group 1;");
        } else {
            asm volatile("cp.async.wait_group 0;");
        }
        __syncthreads();

#pragma unroll
        for (int ks = 0; ks < BK / 8; ks++) {
            const int kb = ks * 8;
            const int kc = kb + (lane & 3);
            uint32_t a[2][4], b[4][2];
#pragma unroll
            for (int mf = 0; mf < 2; mf++) {
                int mr = warp_m * 32 + mf * 16 + (lane >> 2);
                a[mf][0] = f2tf32(As[buf][mr][kc]);
                a[mf][1] = f2tf32(As[buf][mr + 8][kc]);
                a[mf][2] = f2tf32(As[buf][mr][kc + 4]);
                a[mf][3] = f2tf32(As[buf][mr + 8][kc + 4]);
            }
#pragma unroll
            for (int nf = 0; nf < 4; nf++) {
                int nr = warp_n * 32 + nf * 8 + (lane >> 2);
                b[nf][0] = f2tf32(Bs[buf][nr][kc]);
                b[nf][1] = f2tf32(Bs[buf][nr][kc + 4]);
            }
#pragma unroll
            for (int mf = 0; mf < 2; mf++)
#pragma unroll
                for (int nf = 0; nf < 4; nf++) {
                    asm volatile(
                        "mma.sync.aligned.m16n8k8.row.col.f32.tf32.tf32.f32 "
                        "{%0,%1,%2,%3}, {%4,%5,%6,%7}, {%8,%9}, {%0,%1,%2,%3};\n"
                        : "+f"(acc[mf][nf][0]), "+f"(acc[mf][nf][1]),
                          "+f"(acc[mf][nf][2]), "+f"(acc[mf][nf][3])
                        : "r"(a[mf][0]), "r"(a[mf][1]), "r"(a[mf][2]), "r"(a[mf][3]),
                          "r"(b[nf][0]), "r"(b[nf][1]));
                }
        }
        __syncthreads();
    }

#pragma unroll
    for (int mf = 0; mf < 2; mf++) {
#pragma unroll
        for (int nf = 0; nf < 4; nf++) {
            int gr = bm + warp_m * 32 + mf * 16 + (lane >> 2);
            int gc = bn + warp_n * 32 + nf * 8 + 2 * (lane & 3);
            float b0 = 0.f, b1 = 0.f;
            if (BIAS) { b0 = __ldg(bias + gc); b1 = __ldg(bias + gc + 1); }
            if (HALF_OUT) {
                __half* C = (__half*)Cv;
                if (gr < M)
                    *reinterpret_cast<__half2*>(C + (size_t)gr * NTOT + gc) =
                        __floats2half2_rn(acc[mf][nf][0] + b0, acc[mf][nf][1] + b1);
                if (gr + 8 < M)
                    *reinterpret_cast<__half2*>(C + (size_t)(gr + 8) * NTOT + gc) =
                        __floats2half2_rn(acc[mf][nf][2] + b0, acc[mf][nf][3] + b1);
            } else {
                float* C = (float*)Cv;
                if (gr < M)
                    *reinterpret_cast<float2*>(C + (size_t)gr * NTOT + gc) =
                        make_float2(acc[mf][nf][0] + b0, acc[mf][nf][1] + b1);
                if (gr + 8 < M)
                    *reinterpret_cast<float2*>(C + (size_t)(gr + 8) * NTOT + gc) =
                        make_float2(acc[mf][nf][2] + b0, acc[mf][nf][3] + b1);
            }
        }
    }
}

// ---------------------------------------------------------------------------
// fp16-A tensor-core GEMM (GEMM2): A is __half [M,K]; W fp32 [N,K]; C fp32.
// m16n8k16.f16 mma; A fragments are direct LDS.32 (no cvt); W cvt'd at load.
// ---------------------------------------------------------------------------
template <int K, int NTOT, bool BIAS>
__global__ __launch_bounds__(256)
void gemm_f16a(const __half* __restrict__ A, const float* __restrict__ W,
               const float* __restrict__ bias, float* __restrict__ C, int M) {
    constexpr int BM = 128, BN = 64, BK = 32;
    constexpr int LDH = BK + 16;   // 48 halves = 96 B rows (16B-aligned)
    constexpr int LDS = BK + 4;
    constexpr int TILES = K / BK;
    __shared__ __half Ah[2][BM][LDH];
    __shared__ float Bs[2][BN][LDS];

    const int tid = threadIdx.x;
    const int lane = tid & 31;
    const int wid = tid >> 5;
    const int warp_m = wid >> 1;
    const int warp_n = wid & 1;
    const int bm = blockIdx.y * BM;
    const int bn = blockIdx.x * BN;

    float acc[2][4][4];
#pragma unroll
    for (int mf = 0; mf < 2; mf++)
#pragma unroll
        for (int nf = 0; nf < 4; nf++)
#pragma unroll
            for (int r = 0; r < 4; r++) acc[mf][nf][r] = 0.0f;

    auto load_stage = [&](int stage, int k0) {
        // A tile: 128 rows x 4 16B-chunks (8 halves) -> 2 per thread
#pragma unroll
        for (int i = 0; i < 2; i++) {
            int idx = tid + i * 256;
            int row = idx >> 2;
            int ch = (idx & 3) * 8;
            const __half* gp = A + (size_t)(bm + row) * K + k0 + ch;
            uint32_t sa = (uint32_t)__cvta_generic_to_shared(&Ah[stage][row][ch]);
            int sz = (bm + row < M) ? 16 : 0;
            asm volatile("cp.async.cg.shared.global [%0], [%1], 16, %2;"
                         :: "r"(sa), "l"(gp), "r"(sz));
        }
        // B tile: 64 rows x 8 float4 -> 2 per thread
#pragma unroll
        for (int i = 0; i < 2; i++) {
            int idx = tid + i * 256;
            int row = idx >> 3;
            int c4 = (idx & 7) * 4;
            const float* gp = W + (size_t)(bn + row) * K + k0 + c4;
            uint32_t sa = (uint32_t)__cvta_generic_to_shared(&Bs[stage][row][c4]);
            asm volatile("cp.async.cg.shared.global [%0], [%1], 16;"
                         :: "r"(sa), "l"(gp));
        }
        asm volatile("cp.async.commit_group;");
    };

    load_stage(0, 0);

    for (int t = 0; t < TILES; t++) {
        const int buf = t & 1;
        if (t + 1 < TILES) {
            load_stage(buf ^ 1, (t + 1) * BK);
            asm volatile("cp.async.wait_group 1;");
        } else {
            asm volatile("cp.async.wait_group 0;");
        }
        __syncthreads();

#pragma unroll
        for (int ks = 0; ks < BK / 16; ks++) {        // two k16 steps
            const int kb = ks * 16;
            const int kp = kb + 2 * (lane & 3);        // k-pair base
            uint32_t a[2][4], b[4][2];
#pragma unroll
            for (int mf = 0; mf < 2; mf++) {
                int mr = warp_m * 32 + mf * 16 + (lane >> 2);
                a[mf][0] = *reinterpret_cast<const uint32_t*>(&Ah[buf][mr][kp]);
                a[mf][1] = *reinterpret_cast<const uint32_t*>(&Ah[buf][mr + 8][kp]);
                a[mf][2] = *reinterpret_cast<const uint32_t*>(&Ah[buf][mr][kp + 8]);
                a[mf][3] = *reinterpret_cast<const uint32_t*>(&Ah[buf][mr + 8][kp + 8]);
            }
#pragma unroll
            for (int nf = 0; nf < 4; nf++) {
                int nr = warp_n * 32 + nf * 8 + (lane >> 2);
                float2 f0 = *reinterpret_cast<const float2*>(&Bs[buf][nr][kp]);
                float2 f1 = *reinterpret_cast<const float2*>(&Bs[buf][nr][kp + 8]);
                b[nf][0] = pack_f16x2(f0.x, f0.y);
                b[nf][1] = pack_f16x2(f1.x, f1.y);
            }
#pragma unroll
            for (int mf = 0; mf < 2; mf++)
#pragma unroll
                for (int nf = 0; nf < 4; nf++) {
                    asm volatile(
                        "mma.sync.aligned.m16n8k16.row.col.f32.f16.f16.f32 "
                        "{%0,%1,%2,%3}, {%4,%5,%6,%7}, {%8,%9}, {%0,%1,%2,%3};\n"
                        : "+f"(acc[mf][nf][0]), "+f"(acc[mf][nf][1]),
                          "+f"(acc[mf][nf][2]), "+f"(acc[mf][nf][3])
                        : "r"(a[mf][0]), "r"(a[mf][1]), "r"(a[mf][2]), "r"(a[mf][3]),
                          "r"(b[nf][0]), "r"(b[nf][1]));
                }
        }
        __syncthreads();
    }

#pragma unroll
    for (int mf = 0; mf < 2; mf++) {
#pragma unroll
        for (int nf = 0; nf < 4; nf++) {
            int gr = bm + warp_m * 32 + mf * 16 + (lane >> 2);
            int gc = bn + warp_n * 32 + nf * 8 + 2 * (lane & 3);
            float b0 = 0.f, b1 = 0.f;
            if (BIAS) { b0 = __ldg(bias + gc); b1 = __ldg(bias + gc + 1); }
            if (gr < M)
                *reinterpret_cast<float2*>(C + (size_t)gr * NTOT + gc) =
                    make_float2(acc[mf][nf][0] + b0, acc[mf][nf][1] + b1);
            if (gr + 8 < M)
                *reinterpret_cast<float2*>(C + (size_t)(gr + 8) * NTOT + gc) =
                    make_float2(acc[mf][nf][2] + b0, acc[mf][nf][3] + b1);
        }
    }
}

// ---------------------------------------------------------------------------
// CSR construction: histogram -> block sums -> (scan folded into) rowptr -> fill
// ---------------------------------------------------------------------------
__global__ void hist_dst(const int* __restrict__ dst, int* __restrict__ count, int E) {
    int i = blockIdx.x * blockDim.x + threadIdx.x;
    int stride = gridDim.x * blockDim.x;
    for (; i < E; i += stride) {
        int d = dst[i];
        if ((unsigned)d < NN) atomicAdd(count + d, 1);
    }
}

__global__ __launch_bounds__(256)
void block_sums(const int* __restrict__ count, int* __restrict__ bsum) {
    __shared__ int sh[256];
    int i = blockIdx.x * 256 + threadIdx.x;
    sh[threadIdx.x] = (i < NN) ? count[i] : 0;
    __syncthreads();
    for (int off = 128; off > 0; off >>= 1) {
        if (threadIdx.x < off) sh[threadIdx.x] += sh[threadIdx.x + off];
        __syncthreads();
    }
    if (threadIdx.x == 0) bsum[blockIdx.x] = sh[0];
}

// Each block re-scans the (small) bsum array locally, then scans its own
// 256 counts — fuses the old scan_block_sums kernel away.
__global__ __launch_bounds__(256)
void write_rowptr(const int* __restrict__ count, const int* __restrict__ bsum,
                  int* __restrict__ rowptr, int* __restrict__ cursor) {
    __shared__ int sb[256];
    __shared__ int sh[256];
    int t = threadIdx.x;
    int bb = blockIdx.x;

    int bv = (t < NB) ? __ldg(bsum + t) : 0;
    sb[t] = bv;
    int i = bb * 256 + t;
    int v = (i < NN) ? count[i] : 0;
    sh[t] = v;
    __syncthreads();
    for (int off = 1; off < 256; off <<= 1) {
        int addb = (t >= off) ? sb[t - off] : 0;
        int addv = (t >= off) ? sh[t - off] : 0;
        __syncthreads();
        sb[t] += addb;
        sh[t] += addv;
        __syncthreads();
    }
    int boff = sb[bb] - __ldg(bsum + bb);   // exclusive prefix of block bb
    if (i < NN) {
        int rp = boff + sh[t] - v;
        rowptr[i] = rp;
        cursor[i] = rp;
    }
    if (bb == 0 && t == 0) rowptr[NN] = sb[NB - 1] + (NB < 256 ? 0 : 0);
    if (bb == 0 && t == NB - 1) rowptr[NN] = sb[NB - 1];
}

__global__ void fill_csr(const int* __restrict__ ei, int* __restrict__ cursor,
                         int* __restrict__ csr_src, int E) {
    const int* __restrict__ src = ei;
    const int* __restrict__ dst = ei + E;
    int i = blockIdx.x * blockDim.x + threadIdx.x;
    int stride = gridDim.x * blockDim.x;
    for (; i < E; i += stride) {
        int d = dst[i];
        if ((unsigned)d >= NN) continue;
        int pos = atomicAdd(cursor + d, 1);
        csr_src[pos] = src[i];
    }
}

// ---------------------------------------------------------------------------
// fp16 gather aggregation (warp per node). Rows are 128 halves = 32 uint2.
// 8-wide unrolled body for MLP; fp32 accumulation.
// ---------------------------------------------------------------------------
__device__ __forceinline__ void acc_u2(float4& acc, uint2 u, bool relu) {
    float2 fa = __half22float2(*reinterpret_cast<__half2*>(&u.x));
    float2 fb = __half22float2(*reinterpret_cast<__half2*>(&u.y));
    if (relu) {
        fa.x = fmaxf(fa.x, 0.f); fa.y = fmaxf(fa.y, 0.f);
        fb.x = fmaxf(fb.x, 0.f); fb.y = fmaxf(fb.y, 0.f);
    }
    acc.x += fa.x; acc.y += fa.y; acc.z += fb.x; acc.w += fb.y;
}

template <bool RELU, bool BIAS>
__global__ __launch_bounds__(256)
void agg_gather_h16(const uint2* __restrict__ H, const int* __restrict__ rowptr,
                    const int* __restrict__ csr_src, const float* __restrict__ bias,
                    uint2* __restrict__ OUT) {
    const int warp = (blockIdx.x * blockDim.x + threadIdx.x) >> 5;
    const int lane = threadIdx.x & 31;
    if (warp >= NN) return;

    const int start = __ldg(rowptr + warp);
    const int end = __ldg(rowptr + warp + 1);

    float4 acc = BIAS ? __ldg(reinterpret_cast<const float4*>(bias) + lane)
                      : make_float4(0.f, 0.f, 0.f, 0.f);

    int i = start;
    for (; i + 8 <= end; i += 8) {
        int s[8];
#pragma unroll
        for (int j = 0; j < 8; j++) s[j] = __ldg(csr_src + i + j);
        uint2 u[8];
#pragma unroll
        for (int j = 0; j < 8; j++) u[j] = __ldg(H + (size_t)s[j] * 32 + lane);
#pragma unroll
        for (int j = 0; j < 8; j++) acc_u2(acc, u[j], RELU);
    }
    for (; i + 4 <= end; i += 4) {
        int s0 = __ldg(csr_src + i);
        int s1 = __ldg(csr_src + i + 1);
        int s2 = __ldg(csr_src + i + 2);
        int s3 = __ldg(csr_src + i + 3);
        uint2 u0 = __ldg(H + (size_t)s0 * 32 + lane);
        uint2 u1 = __ldg(H + (size_t)s1 * 32 + lane);
        uint2 u2 = __ldg(H + (size_t)s2 * 32 + lane);
        uint2 u3 = __ldg(H + (size_t)s3 * 32 + lane);
        acc_u2(acc, u0, RELU);
        acc_u2(acc, u1, RELU);
        acc_u2(acc, u2, RELU);
        acc_u2(acc, u3, RELU);
    }
    for (; i < end; i++) {
        int s = __ldg(csr_src + i);
        acc_u2(acc, __ldg(H + (size_t)s * 32 + lane), RELU);
    }

    __half2 h0 = __floats2half2_rn(acc.x, acc.y);
    __half2 h1 = __floats2half2_rn(acc.z, acc.w);
    uint2 o;
    o.x = *reinterpret_cast<uint32_t*>(&h0);
    o.y = *reinterpret_cast<uint32_t*>(&h1);
    OUT[(size_t)warp * 32 + lane] = o;
}

extern "C" void kernel_launch(void* const* d_in, const int* in_sizes, int n_in,
                              void* d_out, int out_size) {
    const float* x = (const float*)d_in[0];
    const int* edge_index = (const int*)d_in[1];
    const float* w1 = (const float*)d_in[2];
    const float* b1 = (const float*)d_in[3];
    const float* w2 = (const float*)d_in[4];
    const float* b2 = (const float*)d_in[5];
    float* out = (float*)d_out;

    __half* h1;   cudaGetSymbolAddress((void**)&h1, g_h1);
    __half* agg1; cudaGetSymbolAddress((void**)&agg1, g_agg1);
    __half* agg2; cudaGetSymbolAddress((void**)&agg2, g_agg2);
    int* count;   cudaGetSymbolAddress((void**)&count, g_count);
    int* rowptr;  cudaGetSymbolAddress((void**)&rowptr, g_rowptr);
    int* cursor;  cudaGetSymbolAddress((void**)&cursor, g_cursor);
    int* bsum;    cudaGetSymbolAddress((void**)&bsum, g_blksum);
    int* csr_src; cudaGetSymbolAddress((void**)&csr_src, g_csr_src);

    static cudaStream_t s2 = nullptr;
    static cudaEvent_t ev_fork = nullptr, ev_join = nullptr;
    if (s2 == nullptr) {
        cudaStreamCreateWithFlags(&s2, cudaStreamNonBlocking);
        cudaEventCreateWithFlags(&ev_fork, cudaEventDisableTiming);
        cudaEventCreateWithFlags(&ev_join, cudaEventDisableTiming);
    }

    // ---- Fork: CSR build on s2, concurrent with GEMM1 ----
    cudaEventRecord(ev_fork, 0);
    cudaStreamWaitEvent(s2, ev_fork, 0);

    cudaMemsetAsync(count, 0, NN * sizeof(int), s2);
    hist_dst<<<1024, 256, 0, s2>>>(edge_index + EE, count, EE);
    block_sums<<<NB, 256, 0, s2>>>(count, bsum);
    write_rowptr<<<NB, 256, 0, s2>>>(count, bsum, rowptr, cursor);
    fill_csr<<<1024, 256, 0, s2>>>(edge_index, cursor, csr_src, EE);
    cudaEventRecord(ev_join, s2);

    // ---- h1 = x @ w1^T  -> fp16   (main stream, overlaps CSR build) ----
    {
        dim3 grid(HID_C / 64, (NN + 127) / 128);
        gemm_tf32<IN_C, HID_C, false, true><<<grid, 256>>>(x, w1, nullptr, h1, NN);
    }

    // ---- Join: gathers need both h1 and the CSR ----
    cudaStreamWaitEvent(0, ev_join, 0);

    // ---- agg1[n] = fp16(b1 + sum h1[src in(n)]) ----
    agg_gather_h16<false, true><<<(NN * 32 + 255) / 256, 256>>>(
        (const uint2*)h1, rowptr, csr_src, b1, (uint2*)agg1);
    // ---- agg2[n] = fp16 sum relu(agg1[src in(n)]) ----
    agg_gather_h16<true, false><<<(NN * 32 + 255) / 256, 256>>>(
        (const uint2*)agg1, rowptr, csr_src, nullptr, (uint2*)agg2);
    // ---- out = agg2 @ w2^T + b2   (fp16-A mma) ----
    {
        dim3 grid(OUT_C / 64, (NN + 127) / 128);
        gemm_f16a<HID_C, OUT_C, true><<<grid, 256>>>(agg2, w2, b2, out, NN);
    }
}